// round 15
// baseline (speedup 1.0000x reference)
#include <cuda_runtime.h>
#include <math.h>
#include <float.h>

#define Bn 32
#define Cn 512
#define CR 64
#define Hd 64
#define Wd 64
#define HW 4096
#define EPS 1e-12f

// ---- scratch (no allocation allowed) ----
__device__ float g_avg[Bn * Cn];
__device__ float g_mx [Bn * Cn];
__device__ float g_s  [Bn * Cn];
__device__ float g_sv [4];
__device__ float g_ca [Bn * HW];
__device__ float g_cm [Bn * HW];
__device__ float g_sig[Bn * HW];

// ============================================================
// K1: block 0 = spectral norms (verified 512-thread body);
// blocks 1..4096 = stats, k_out-style dense reads:
// 4 contiguous rows per block, 8 independent float4 loads/thread,
// register accumulation, single reduce tail at block end.
// grid = 4097, block = 512.
// ============================================================
__global__ void __launch_bounds__(512)
k_stats(const float* __restrict__ x,
        const float* __restrict__ w1, const float* __restrict__ u1,
        const float* __restrict__ w2, const float* __restrict__ u2,
        const float* __restrict__ w3) {
    int t = threadIdx.x;

    if (blockIdx.x == 0) {
        // ---------------- spectral norms, 512 threads ----------------
        __shared__ float buf[Cn];
        __shared__ float red[Cn];
        int o8 = t >> 3, k8 = t & 7;

        // ----- sv1 : Wm1 [64, 512] -----
        float v = 0.f;
#pragma unroll 8
        for (int i = 0; i < CR; i++) v += u1[i] * w1[i * Cn + t];
        red[t] = v * v;
        __syncthreads();
        for (int o = 256; o; o >>= 1) { if (t < o) red[t] += red[t + o]; __syncthreads(); }
        float nv = sqrtf(red[0]);
        __syncthreads();
        buf[t] = v / fmaxf(nv, EPS);
        __syncthreads();
        {
            float tv = 0.f;
#pragma unroll 8
            for (int j = k8 * 64; j < k8 * 64 + 64; j++) tv += w1[o8 * Cn + j] * buf[j];
#pragma unroll
            for (int o = 4; o; o >>= 1) tv += __shfl_down_sync(0xffffffffu, tv, o, 8);
            __syncthreads();
            if (k8 == 0) red[o8] = tv * tv;
            __syncthreads();
            if (t < 32) {
                float r = red[t] + red[t + 32];
#pragma unroll
                for (int o = 16; o; o >>= 1) r += __shfl_down_sync(0xffffffffu, r, o);
                if (t == 0) { float nt = sqrtf(r); g_sv[0] = nt * nt / fmaxf(nt, EPS); }
            }
            __syncthreads();
        }

        // ----- sv2 : Wm2 [512, 64] -----
        {
            float v2 = 0.f;
#pragma unroll 8
            for (int i = k8 * 64; i < k8 * 64 + 64; i++) v2 += u2[i] * w2[i * CR + o8];
#pragma unroll
            for (int o = 4; o; o >>= 1) v2 += __shfl_down_sync(0xffffffffu, v2, o, 8);
            __syncthreads();
            if (k8 == 0) red[o8] = v2 * v2;
            __syncthreads();
            if (t < 32) {
                float r = red[t] + red[t + 32];
#pragma unroll
                for (int o = 16; o; o >>= 1) r += __shfl_down_sync(0xffffffffu, r, o);
                if (t == 0) red[0] = sqrtf(r);
            }
            __syncthreads();
            float n2 = red[0];
            __syncthreads();
            if (k8 == 0) buf[o8] = v2 / fmaxf(n2, EPS);
            __syncthreads();
            float t2 = 0.f;
#pragma unroll 8
            for (int j = 0; j < CR; j++) t2 += w2[t * CR + j] * buf[j];
            red[t] = t2 * t2;
            __syncthreads();
            for (int o = 256; o; o >>= 1) { if (t < o) red[t] += red[t + o]; __syncthreads(); }
            if (t == 0) { float nt = sqrtf(red[0]); g_sv[1] = nt * nt / fmaxf(nt, EPS); }
        }

        // ----- sv3 = ||w3||_F -----
        if (t == 0) {
            float nn = 0.f;
            for (int k = 0; k < 18; k++) nn += w3[k] * w3[k];
            g_sv[2] = sqrtf(nn);
        }
        return;
    }

    // ---------------- stats: 4 rows per block, dense reads ----------------
    int idx = blockIdx.x - 1;                 // 0..4095
    int bc0 = idx * 4;                        // first of 4 contiguous (b,c) rows
    const float4* p = reinterpret_cast<const float4*>(x) + (size_t)bc0 * (HW / 4);
    float s0 = 0.f, s1 = 0.f, s2 = 0.f, s3 = 0.f;
    float m0 = -FLT_MAX, m1 = -FLT_MAX, m2 = -FLT_MAX, m3 = -FLT_MAX;
    // row r = p[r*1024 .. r*1024+1023]; thread reads k*512 + t for k=0,1
#pragma unroll
    for (int k = 0; k < 2; k++) {
        float4 v0 = p[0 * 1024 + k * 512 + t];
        float4 v1 = p[1 * 1024 + k * 512 + t];
        float4 v2 = p[2 * 1024 + k * 512 + t];
        float4 v3 = p[3 * 1024 + k * 512 + t];
        s0 += (v0.x + v0.y) + (v0.z + v0.w);
        m0 = fmaxf(m0, fmaxf(fmaxf(v0.x, v0.y), fmaxf(v0.z, v0.w)));
        s1 += (v1.x + v1.y) + (v1.z + v1.w);
        m1 = fmaxf(m1, fmaxf(fmaxf(v1.x, v1.y), fmaxf(v1.z, v1.w)));
        s2 += (v2.x + v2.y) + (v2.z + v2.w);
        m2 = fmaxf(m2, fmaxf(fmaxf(v2.x, v2.y), fmaxf(v2.z, v2.w)));
        s3 += (v3.x + v3.y) + (v3.z + v3.w);
        m3 = fmaxf(m3, fmaxf(fmaxf(v3.x, v3.y), fmaxf(v3.z, v3.w)));
    }
    // warp reduce all 4 pairs
#pragma unroll
    for (int o = 16; o; o >>= 1) {
        s0 += __shfl_down_sync(0xffffffffu, s0, o);
        s1 += __shfl_down_sync(0xffffffffu, s1, o);
        s2 += __shfl_down_sync(0xffffffffu, s2, o);
        s3 += __shfl_down_sync(0xffffffffu, s3, o);
        m0 = fmaxf(m0, __shfl_down_sync(0xffffffffu, m0, o));
        m1 = fmaxf(m1, __shfl_down_sync(0xffffffffu, m1, o));
        m2 = fmaxf(m2, __shfl_down_sync(0xffffffffu, m2, o));
        m3 = fmaxf(m3, __shfl_down_sync(0xffffffffu, m3, o));
    }
    __shared__ float wsum[16][4];
    __shared__ float wmax[16][4];
    int warp = t >> 5, lane = t & 31;
    if (lane == 0) {
        wsum[warp][0] = s0; wsum[warp][1] = s1; wsum[warp][2] = s2; wsum[warp][3] = s3;
        wmax[warp][0] = m0; wmax[warp][1] = m1; wmax[warp][2] = m2; wmax[warp][3] = m3;
    }
    __syncthreads();
    // warps 0..3: warp w reduces row w across the 16 warp-partials
    if (warp < 4 && lane < 16) {
        float a = wsum[lane][warp];
        float b = wmax[lane][warp];
#pragma unroll
        for (int o = 8; o; o >>= 1) {
            a += __shfl_down_sync(0x0000ffffu, a, o, 16);
            b = fmaxf(b, __shfl_down_sync(0x0000ffffu, b, o, 16));
        }
        if (lane == 0) {
            g_avg[bc0 + warp] = a * (1.f / HW);
            g_mx [bc0 + warp] = b;
        }
    }
}

// ============================================================
// K2: channel-attention MLP + sigmoid -> s[B,C]. (sv precomputed)
// grid = 32, block = 512. Hidden layer: 8 threads per output.
// ============================================================
__global__ void k_mlp(const float* __restrict__ w1, const float* __restrict__ b1,
                      const float* __restrict__ w2, const float* __restrict__ b2) {
    int b = blockIdx.x, t = threadIdx.x;
    int o8 = t >> 3, k8 = t & 7;
    __shared__ float sa[Cn], sx[Cn], ha[CR], hm[CR];
    sa[t] = g_avg[b * Cn + t];
    sx[t] = g_mx [b * Cn + t];
    __syncthreads();
    float inv1 = 1.f / g_sv[0];
    float inv2 = 1.f / g_sv[1];
    {
        float xa = 0.f, xm = 0.f;
#pragma unroll 8
        for (int c = k8 * 64; c < k8 * 64 + 64; c++) {
            float w = w1[o8 * Cn + c];
            xa += w * sa[c];
            xm += w * sx[c];
        }
#pragma unroll
        for (int o = 4; o; o >>= 1) {
            xa += __shfl_down_sync(0xffffffffu, xa, o, 8);
            xm += __shfl_down_sync(0xffffffffu, xm, o, 8);
        }
        if (k8 == 0) {
            float bb = b1[o8];
            ha[o8] = fmaxf(xa * inv1 + bb, 0.f);
            hm[o8] = fmaxf(xm * inv1 + bb, 0.f);
        }
    }
    __syncthreads();
    float a = 0.f, m = 0.f;
#pragma unroll 8
    for (int k = 0; k < CR; k++) {
        float w = w2[t * CR + k];
        a += w * ha[k];
        m += w * hm[k];
    }
    float bb = b2[t];
    a = a * inv2 + bb;
    m = m * inv2 + bb;
    g_s[b * Cn + t] = 1.f / (1.f + expf(-(a + m)));
}

// ============================================================
// K3: per-pixel mean/max over channels of x*s -> ca, cm.
// grid = (32, 32), block = 512 = 16 chan-chunks x 32 float4-groups.
// (measured: 77% DRAM, 45us)
// ============================================================
__global__ void k_pool(const float* __restrict__ x) {
    int b = blockIdx.y;
    int p0 = blockIdx.x * 128;           // 128 pixels per block
    int tid = threadIdx.x;
    int g  = tid & 31;                   // float4 pixel-group 0..31
    int ch = tid >> 5;                   // channel-chunk 0..15
    __shared__ float ss[Cn];
    __shared__ float4 rs[16][32];
    __shared__ float4 rm[16][32];
    ss[tid] = g_s[b * Cn + tid];
    __syncthreads();

    const float* xb = x + (size_t)b * Cn * HW + p0 + g * 4;
    float4 sum = make_float4(0.f, 0.f, 0.f, 0.f);
    float4 mx  = make_float4(-FLT_MAX, -FLT_MAX, -FLT_MAX, -FLT_MAX);
#pragma unroll 8
    for (int cc = 0; cc < 32; cc++) {
        int c = ch * 32 + cc;
        float4 v = *reinterpret_cast<const float4*>(xb + (size_t)c * HW);
        float s = ss[c];
        v.x *= s; v.y *= s; v.z *= s; v.w *= s;
        sum.x += v.x; sum.y += v.y; sum.z += v.z; sum.w += v.w;
        mx.x = fmaxf(mx.x, v.x); mx.y = fmaxf(mx.y, v.y);
        mx.z = fmaxf(mx.z, v.z); mx.w = fmaxf(mx.w, v.w);
    }
    rs[ch][g] = sum; rm[ch][g] = mx;
    __syncthreads();
#pragma unroll
    for (int o = 8; o; o >>= 1) {
        if (ch < o) {
            float4 a = rs[ch][g], c2 = rs[ch + o][g];
            a.x += c2.x; a.y += c2.y; a.z += c2.z; a.w += c2.w;
            rs[ch][g] = a;
            float4 m1 = rm[ch][g], m2 = rm[ch + o][g];
            m1.x = fmaxf(m1.x, m2.x); m1.y = fmaxf(m1.y, m2.y);
            m1.z = fmaxf(m1.z, m2.z); m1.w = fmaxf(m1.w, m2.w);
            rm[ch][g] = m1;
        }
        __syncthreads();
    }
    if (ch == 0) {
        float4 a = rs[0][g];
        a.x *= (1.f / Cn); a.y *= (1.f / Cn); a.z *= (1.f / Cn); a.w *= (1.f / Cn);
        *reinterpret_cast<float4*>(g_ca + b * HW + p0 + g * 4) = a;
        *reinterpret_cast<float4*>(g_cm + b * HW + p0 + g * 4) = rm[0][g];
    }
}

// ============================================================
// K4: 3x3 conv on (ca, cm) -> g_sig = sigmoid(y).
// ca/cm are L2-resident (1 MB). grid = (16, 32), block = 256.
// ============================================================
__global__ void k_conv(const float* __restrict__ w3, const float* __restrict__ b3) {
    int b = blockIdx.y;
    int p = blockIdx.x * 256 + threadIdx.x;
    int h = p >> 6, w = p & 63;
    __shared__ float wc[20];
    if (threadIdx.x < 18) wc[threadIdx.x] = w3[threadIdx.x];
    if (threadIdx.x == 18) wc[18] = b3[0];
    if (threadIdx.x == 19) wc[19] = 1.f / g_sv[2];
    __syncthreads();

    const float* ca = g_ca + b * HW;
    const float* cm = g_cm + b * HW;
    float y = 0.f;
#pragma unroll
    for (int dy = -1; dy <= 1; dy++) {
        int hh = h + dy;
        if (hh < 0 || hh >= Hd) continue;
#pragma unroll
        for (int dx = -1; dx <= 1; dx++) {
            int ww = w + dx;
            if (ww < 0 || ww >= Wd) continue;
            int q = hh * Wd + ww;
            int ki = (dy + 1) * 3 + (dx + 1);
            y += wc[ki] * ca[q] + wc[9 + ki] * cm[q];
        }
    }
    y = y * wc[19] + wc[18];
    g_sig[b * HW + p] = 1.f / (1.f + expf(-y));
}

// ============================================================
// K5: pointwise out = x * s[b,c] * sig[b,p], 2 channels/block.
// (measured best: 76.2us @ 80.4% DRAM). grid = 8192, block = 256.
// ============================================================
__global__ void k_out(const float* __restrict__ x, float* __restrict__ out) {
    int blk = blockIdx.x;                // 0..8191
    int b = blk >> 8;                    // /256
    int c0 = (blk & 255) * 2;
    float s0 = g_s[b * Cn + c0];
    float s1 = g_s[b * Cn + c0 + 1];
    const float4* x0 = reinterpret_cast<const float4*>(x + ((size_t)b * Cn + c0) * HW);
    const float4* x1 = x0 + HW / 4;
    float4* o0 = reinterpret_cast<float4*>(out + ((size_t)b * Cn + c0) * HW);
    float4* o1 = o0 + HW / 4;
    const float4* sg = reinterpret_cast<const float4*>(g_sig + b * HW);
    int tid = threadIdx.x;
#pragma unroll
    for (int k = 0; k < 4; k++) {
        int i = k * 256 + tid;
        float4 gv = sg[i];
        float4 v0 = __ldcs(x0 + i);
        float4 v1 = __ldcs(x1 + i);
        v0.x *= s0 * gv.x; v0.y *= s0 * gv.y; v0.z *= s0 * gv.z; v0.w *= s0 * gv.w;
        v1.x *= s1 * gv.x; v1.y *= s1 * gv.y; v1.z *= s1 * gv.z; v1.w *= s1 * gv.w;
        __stcs(o0 + i, v0);
        __stcs(o1 + i, v1);
    }
}

// ============================================================
extern "C" void kernel_launch(void* const* d_in, const int* in_sizes, int n_in,
                              void* d_out, int out_size) {
    const float* x  = (const float*)d_in[0];
    const float* w1 = (const float*)d_in[1];
    const float* b1 = (const float*)d_in[2];
    const float* u1 = (const float*)d_in[3];
    const float* w2 = (const float*)d_in[4];
    const float* b2 = (const float*)d_in[5];
    const float* u2 = (const float*)d_in[6];
    const float* w3 = (const float*)d_in[7];
    const float* b3 = (const float*)d_in[8];
    // d_in[9] = u3: unused (sv3 reduces to ||w3||_F)
    float* out = (float*)d_out;

    k_stats<<<1 + Bn * Cn / 4, 512>>>(x, w1, u1, w2, u2, w3);
    k_mlp<<<Bn, Cn>>>(w1, b1, w2, b2);
    k_pool<<<dim3(HW / 128, Bn), 512>>>(x);
    k_conv<<<dim3(HW / 256, Bn), 256>>>(w3, b3);
    k_out<<<Bn * Cn / 2, 256>>>(x, out);
}

// round 16
// speedup vs baseline: 1.0157x; 1.0157x over previous
#include <cuda_runtime.h>
#include <math.h>
#include <float.h>

#define Bn 32
#define Cn 512
#define CR 64
#define Hd 64
#define Wd 64
#define HW 4096
#define EPS 1e-12f

// ---- scratch (no allocation allowed) ----
__device__ float g_avg[Bn * Cn];
__device__ float g_mx [Bn * Cn];
__device__ float g_s  [Bn * Cn];
__device__ float g_sv [4];
__device__ float g_ca [Bn * HW];
__device__ float g_cm [Bn * HW];
__device__ float g_sig[Bn * HW];

// ---- PTX helpers ----
__device__ __forceinline__ unsigned s2u(const void* p) {
    unsigned a;
    asm("{ .reg .u64 t; cvta.to.shared.u64 t, %1; cvt.u32.u64 %0, t; }"
        : "=r"(a) : "l"(p));
    return a;
}
#define MBINIT(addr, cnt) \
    asm volatile("mbarrier.init.shared.b64 [%0], %1;" :: "r"(addr), "r"(cnt) : "memory")
#define MBEXPECT(addr, tx) \
    asm volatile("mbarrier.arrive.expect_tx.shared.b64 _, [%0], %1;" :: "r"(addr), "r"(tx) : "memory")
#define BULKCP(dst, src, sz, mbar) \
    asm volatile("cp.async.bulk.shared::cta.global.mbarrier::complete_tx::bytes [%0], [%1], %2, [%3];" \
                 :: "r"(dst), "l"(src), "r"(sz), "r"(mbar) : "memory")
#define MBWAIT(mbar_addr, parity) do { \
    unsigned _m = (mbar_addr), _p = (parity), _d; \
    asm volatile("{ .reg .pred p; mbarrier.try_wait.parity.acquire.cta.shared::cta.b64 p, [%1], %2; selp.b32 %0, 1, 0, p; }" \
        : "=r"(_d) : "r"(_m), "r"(_p) : "memory"); \
    if (!_d) { \
        asm volatile("{ .reg .pred P1; WL_%=: mbarrier.try_wait.parity.acquire.cta.shared::cta.b64 P1, [%0], %1, 0x989680; @P1 bra.uni WD_%=; bra.uni WL_%=; WD_%=: }" \
            :: "r"(_m), "r"(_p) : "memory"); \
    } \
} while (0)

// ============================================================
// K1: block 0 = spectral norms; blocks 1..4096 = stats via
// cp.async.bulk double-buffered pipeline: 4 rows (64 KB) per
// block, 2 x 16 KB smem buffers, 4 stages, reduce from smem.
// grid = 4097, block = 512.
// ============================================================
__global__ void __launch_bounds__(512)
k_stats(const float* __restrict__ x,
        const float* __restrict__ w1, const float* __restrict__ u1,
        const float* __restrict__ w2, const float* __restrict__ u2,
        const float* __restrict__ w3) {
    int t = threadIdx.x;
    __shared__ alignas(128) float stage[2 * 4096];     // 2 x 16 KB
    __shared__ alignas(8) unsigned long long mbar[2];

    if (blockIdx.x == 0) {
        // ---------------- spectral norms, 512 threads ----------------
        __shared__ float buf[Cn];
        __shared__ float red[Cn];
        int o8 = t >> 3, k8 = t & 7;

        // ----- sv1 : Wm1 [64, 512] -----
        float v = 0.f;
#pragma unroll 8
        for (int i = 0; i < CR; i++) v += u1[i] * w1[i * Cn + t];
        red[t] = v * v;
        __syncthreads();
        for (int o = 256; o; o >>= 1) { if (t < o) red[t] += red[t + o]; __syncthreads(); }
        float nv = sqrtf(red[0]);
        __syncthreads();
        buf[t] = v / fmaxf(nv, EPS);
        __syncthreads();
        {
            float tv = 0.f;
#pragma unroll 8
            for (int j = k8 * 64; j < k8 * 64 + 64; j++) tv += w1[o8 * Cn + j] * buf[j];
#pragma unroll
            for (int o = 4; o; o >>= 1) tv += __shfl_down_sync(0xffffffffu, tv, o, 8);
            __syncthreads();
            if (k8 == 0) red[o8] = tv * tv;
            __syncthreads();
            if (t < 32) {
                float r = red[t] + red[t + 32];
#pragma unroll
                for (int o = 16; o; o >>= 1) r += __shfl_down_sync(0xffffffffu, r, o);
                if (t == 0) { float nt = sqrtf(r); g_sv[0] = nt * nt / fmaxf(nt, EPS); }
            }
            __syncthreads();
        }

        // ----- sv2 : Wm2 [512, 64] -----
        {
            float v2 = 0.f;
#pragma unroll 8
            for (int i = k8 * 64; i < k8 * 64 + 64; i++) v2 += u2[i] * w2[i * CR + o8];
#pragma unroll
            for (int o = 4; o; o >>= 1) v2 += __shfl_down_sync(0xffffffffu, v2, o, 8);
            __syncthreads();
            if (k8 == 0) red[o8] = v2 * v2;
            __syncthreads();
            if (t < 32) {
                float r = red[t] + red[t + 32];
#pragma unroll
                for (int o = 16; o; o >>= 1) r += __shfl_down_sync(0xffffffffu, r, o);
                if (t == 0) red[0] = sqrtf(r);
            }
            __syncthreads();
            float n2 = red[0];
            __syncthreads();
            if (k8 == 0) buf[o8] = v2 / fmaxf(n2, EPS);
            __syncthreads();
            float t2 = 0.f;
#pragma unroll 8
            for (int j = 0; j < CR; j++) t2 += w2[t * CR + j] * buf[j];
            red[t] = t2 * t2;
            __syncthreads();
            for (int o = 256; o; o >>= 1) { if (t < o) red[t] += red[t + o]; __syncthreads(); }
            if (t == 0) { float nt = sqrtf(red[0]); g_sv[1] = nt * nt / fmaxf(nt, EPS); }
        }

        // ----- sv3 = ||w3||_F -----
        if (t == 0) {
            float nn = 0.f;
            for (int k = 0; k < 18; k++) nn += w3[k] * w3[k];
            g_sv[2] = sqrtf(nn);
        }
        return;
    }

    // ---------------- stats: bulk-copy pipeline, 4 rows/block ----------------
    int idx = blockIdx.x - 1;                 // 0..4095
    int bc0 = idx * 4;
    const char* src = reinterpret_cast<const char*>(x) + (size_t)bc0 * HW * 4;
    unsigned sb = s2u(stage);
    unsigned mb0 = s2u(&mbar[0]);
    unsigned mb1 = s2u(&mbar[1]);

    if (t == 0) { MBINIT(mb0, 1); MBINIT(mb1, 1); }
    __syncthreads();
    if (t == 0) {
        MBEXPECT(mb0, 16384u); BULKCP(sb,          src,         16384u, mb0);
        MBEXPECT(mb1, 16384u); BULKCP(sb + 16384u, src + 16384, 16384u, mb1);
    }

    float sa[4], ma[4];
#pragma unroll
    for (int s = 0; s < 4; s++) { sa[s] = 0.f; ma[s] = -FLT_MAX; }

#pragma unroll
    for (int s = 0; s < 4; s++) {
        unsigned m = (s & 1) ? mb1 : mb0;
        MBWAIT(m, (unsigned)(s >> 1));
        const float4* buf4 = reinterpret_cast<const float4*>(stage + (s & 1) * 4096);
        float4 v0 = buf4[t];
        float4 v1 = buf4[512 + t];
        sa[s] += ((v0.x + v0.y) + (v0.z + v0.w)) + ((v1.x + v1.y) + (v1.z + v1.w));
        float mm = fmaxf(fmaxf(fmaxf(v0.x, v0.y), fmaxf(v0.z, v0.w)),
                         fmaxf(fmaxf(v1.x, v1.y), fmaxf(v1.z, v1.w)));
        ma[s] = fmaxf(ma[s], mm);
        __syncthreads();
        if (s < 2 && t == 0) {
            MBEXPECT(m, 16384u);
            BULKCP(sb + (unsigned)(s & 1) * 16384u, src + (size_t)(s + 2) * 16384, 16384u, m);
        }
    }

    // ---- tail reduce (verified R15 structure) ----
#pragma unroll
    for (int o = 16; o; o >>= 1) {
        sa[0] += __shfl_down_sync(0xffffffffu, sa[0], o);
        sa[1] += __shfl_down_sync(0xffffffffu, sa[1], o);
        sa[2] += __shfl_down_sync(0xffffffffu, sa[2], o);
        sa[3] += __shfl_down_sync(0xffffffffu, sa[3], o);
        ma[0] = fmaxf(ma[0], __shfl_down_sync(0xffffffffu, ma[0], o));
        ma[1] = fmaxf(ma[1], __shfl_down_sync(0xffffffffu, ma[1], o));
        ma[2] = fmaxf(ma[2], __shfl_down_sync(0xffffffffu, ma[2], o));
        ma[3] = fmaxf(ma[3], __shfl_down_sync(0xffffffffu, ma[3], o));
    }
    __shared__ float wsum[16][4];
    __shared__ float wmax[16][4];
    int warp = t >> 5, lane = t & 31;
    if (lane == 0) {
#pragma unroll
        for (int r = 0; r < 4; r++) { wsum[warp][r] = sa[r]; wmax[warp][r] = ma[r]; }
    }
    __syncthreads();
    if (warp < 4 && lane < 16) {
        float a = wsum[lane][warp];
        float b = wmax[lane][warp];
#pragma unroll
        for (int o = 8; o; o >>= 1) {
            a += __shfl_down_sync(0x0000ffffu, a, o, 16);
            b = fmaxf(b, __shfl_down_sync(0x0000ffffu, b, o, 16));
        }
        if (lane == 0) {
            g_avg[bc0 + warp] = a * (1.f / HW);
            g_mx [bc0 + warp] = b;
        }
    }
}

// ============================================================
// K2: channel-attention MLP + sigmoid -> s[B,C]. (sv precomputed)
// grid = 32, block = 512. Hidden layer: 8 threads per output.
// ============================================================
__global__ void k_mlp(const float* __restrict__ w1, const float* __restrict__ b1,
                      const float* __restrict__ w2, const float* __restrict__ b2) {
    int b = blockIdx.x, t = threadIdx.x;
    int o8 = t >> 3, k8 = t & 7;
    __shared__ float sa[Cn], sx[Cn], ha[CR], hm[CR];
    sa[t] = g_avg[b * Cn + t];
    sx[t] = g_mx [b * Cn + t];
    __syncthreads();
    float inv1 = 1.f / g_sv[0];
    float inv2 = 1.f / g_sv[1];
    {
        float xa = 0.f, xm = 0.f;
#pragma unroll 8
        for (int c = k8 * 64; c < k8 * 64 + 64; c++) {
            float w = w1[o8 * Cn + c];
            xa += w * sa[c];
            xm += w * sx[c];
        }
#pragma unroll
        for (int o = 4; o; o >>= 1) {
            xa += __shfl_down_sync(0xffffffffu, xa, o, 8);
            xm += __shfl_down_sync(0xffffffffu, xm, o, 8);
        }
        if (k8 == 0) {
            float bb = b1[o8];
            ha[o8] = fmaxf(xa * inv1 + bb, 0.f);
            hm[o8] = fmaxf(xm * inv1 + bb, 0.f);
        }
    }
    __syncthreads();
    float a = 0.f, m = 0.f;
#pragma unroll 8
    for (int k = 0; k < CR; k++) {
        float w = w2[t * CR + k];
        a += w * ha[k];
        m += w * hm[k];
    }
    float bb = b2[t];
    a = a * inv2 + bb;
    m = m * inv2 + bb;
    g_s[b * Cn + t] = 1.f / (1.f + expf(-(a + m)));
}

// ============================================================
// K3: per-pixel mean/max over channels of x*s -> ca, cm.
// grid = (32, 32), block = 512 = 16 chan-chunks x 32 float4-groups.
// (measured: 77% DRAM, 45us)
// ============================================================
__global__ void k_pool(const float* __restrict__ x) {
    int b = blockIdx.y;
    int p0 = blockIdx.x * 128;           // 128 pixels per block
    int tid = threadIdx.x;
    int g  = tid & 31;                   // float4 pixel-group 0..31
    int ch = tid >> 5;                   // channel-chunk 0..15
    __shared__ float ss[Cn];
    __shared__ float4 rs[16][32];
    __shared__ float4 rm[16][32];
    ss[tid] = g_s[b * Cn + tid];
    __syncthreads();

    const float* xb = x + (size_t)b * Cn * HW + p0 + g * 4;
    float4 sum = make_float4(0.f, 0.f, 0.f, 0.f);
    float4 mx  = make_float4(-FLT_MAX, -FLT_MAX, -FLT_MAX, -FLT_MAX);
#pragma unroll 8
    for (int cc = 0; cc < 32; cc++) {
        int c = ch * 32 + cc;
        float4 v = *reinterpret_cast<const float4*>(xb + (size_t)c * HW);
        float s = ss[c];
        v.x *= s; v.y *= s; v.z *= s; v.w *= s;
        sum.x += v.x; sum.y += v.y; sum.z += v.z; sum.w += v.w;
        mx.x = fmaxf(mx.x, v.x); mx.y = fmaxf(mx.y, v.y);
        mx.z = fmaxf(mx.z, v.z); mx.w = fmaxf(mx.w, v.w);
    }
    rs[ch][g] = sum; rm[ch][g] = mx;
    __syncthreads();
#pragma unroll
    for (int o = 8; o; o >>= 1) {
        if (ch < o) {
            float4 a = rs[ch][g], c2 = rs[ch + o][g];
            a.x += c2.x; a.y += c2.y; a.z += c2.z; a.w += c2.w;
            rs[ch][g] = a;
            float4 m1 = rm[ch][g], m2 = rm[ch + o][g];
            m1.x = fmaxf(m1.x, m2.x); m1.y = fmaxf(m1.y, m2.y);
            m1.z = fmaxf(m1.z, m2.z); m1.w = fmaxf(m1.w, m2.w);
            rm[ch][g] = m1;
        }
        __syncthreads();
    }
    if (ch == 0) {
        float4 a = rs[0][g];
        a.x *= (1.f / Cn); a.y *= (1.f / Cn); a.z *= (1.f / Cn); a.w *= (1.f / Cn);
        *reinterpret_cast<float4*>(g_ca + b * HW + p0 + g * 4) = a;
        *reinterpret_cast<float4*>(g_cm + b * HW + p0 + g * 4) = rm[0][g];
    }
}

// ============================================================
// K4: 3x3 conv on (ca, cm) -> g_sig = sigmoid(y).
// ca/cm are L2-resident (1 MB). grid = (16, 32), block = 256.
// ============================================================
__global__ void k_conv(const float* __restrict__ w3, const float* __restrict__ b3) {
    int b = blockIdx.y;
    int p = blockIdx.x * 256 + threadIdx.x;
    int h = p >> 6, w = p & 63;
    __shared__ float wc[20];
    if (threadIdx.x < 18) wc[threadIdx.x] = w3[threadIdx.x];
    if (threadIdx.x == 18) wc[18] = b3[0];
    if (threadIdx.x == 19) wc[19] = 1.f / g_sv[2];
    __syncthreads();

    const float* ca = g_ca + b * HW;
    const float* cm = g_cm + b * HW;
    float y = 0.f;
#pragma unroll
    for (int dy = -1; dy <= 1; dy++) {
        int hh = h + dy;
        if (hh < 0 || hh >= Hd) continue;
#pragma unroll
        for (int dx = -1; dx <= 1; dx++) {
            int ww = w + dx;
            if (ww < 0 || ww >= Wd) continue;
            int q = hh * Wd + ww;
            int ki = (dy + 1) * 3 + (dx + 1);
            y += wc[ki] * ca[q] + wc[9 + ki] * cm[q];
        }
    }
    y = y * wc[19] + wc[18];
    g_sig[b * HW + p] = 1.f / (1.f + expf(-y));
}

// ============================================================
// K5: pointwise out = x * s[b,c] * sig[b,p], 2 channels/block.
// (measured best: 76.2us @ 80.4% DRAM). grid = 8192, block = 256.
// ============================================================
__global__ void k_out(const float* __restrict__ x, float* __restrict__ out) {
    int blk = blockIdx.x;                // 0..8191
    int b = blk >> 8;                    // /256
    int c0 = (blk & 255) * 2;
    float s0 = g_s[b * Cn + c0];
    float s1 = g_s[b * Cn + c0 + 1];
    const float4* x0 = reinterpret_cast<const float4*>(x + ((size_t)b * Cn + c0) * HW);
    const float4* x1 = x0 + HW / 4;
    float4* o0 = reinterpret_cast<float4*>(out + ((size_t)b * Cn + c0) * HW);
    float4* o1 = o0 + HW / 4;
    const float4* sg = reinterpret_cast<const float4*>(g_sig + b * HW);
    int tid = threadIdx.x;
#pragma unroll
    for (int k = 0; k < 4; k++) {
        int i = k * 256 + tid;
        float4 gv = sg[i];
        float4 v0 = __ldcs(x0 + i);
        float4 v1 = __ldcs(x1 + i);
        v0.x *= s0 * gv.x; v0.y *= s0 * gv.y; v0.z *= s0 * gv.z; v0.w *= s0 * gv.w;
        v1.x *= s1 * gv.x; v1.y *= s1 * gv.y; v1.z *= s1 * gv.z; v1.w *= s1 * gv.w;
        __stcs(o0 + i, v0);
        __stcs(o1 + i, v1);
    }
}

// ============================================================
extern "C" void kernel_launch(void* const* d_in, const int* in_sizes, int n_in,
                              void* d_out, int out_size) {
    const float* x  = (const float*)d_in[0];
    const float* w1 = (const float*)d_in[1];
    const float* b1 = (const float*)d_in[2];
    const float* u1 = (const float*)d_in[3];
    const float* w2 = (const float*)d_in[4];
    const float* b2 = (const float*)d_in[5];
    const float* u2 = (const float*)d_in[6];
    const float* w3 = (const float*)d_in[7];
    const float* b3 = (const float*)d_in[8];
    // d_in[9] = u3: unused (sv3 reduces to ||w3||_F)
    float* out = (float*)d_out;

    k_stats<<<1 + Bn * Cn / 4, 512>>>(x, w1, u1, w2, u2, w3);
    k_mlp<<<Bn, Cn>>>(w1, b1, w2, b2);
    k_pool<<<dim3(HW / 128, Bn), 512>>>(x);
    k_conv<<<dim3(HW / 256, Bn), 256>>>(w3, b3);
    k_out<<<Bn * Cn / 2, 256>>>(x, out);
}

// round 17
// speedup vs baseline: 1.0266x; 1.0107x over previous
#include <cuda_runtime.h>
#include <math.h>
#include <float.h>

#define Bn 32
#define Cn 512
#define CR 64
#define Hd 64
#define Wd 64
#define HW 4096
#define EPS 1e-12f

// ---- scratch (no allocation allowed) ----
__device__ float g_avg[Bn * Cn];
__device__ float g_mx [Bn * Cn];
__device__ float g_s  [Bn * Cn];
__device__ float g_sv [4];
__device__ float g_ca [Bn * HW];
__device__ float g_cm [Bn * HW];
__device__ float g_sig[Bn * HW];

// epoch-safe monotonic counters (graph replays keep incrementing)
__device__ unsigned c_pool [Bn];      // arrivals: 32 pool blocks per batch per epoch
__device__ unsigned t_conv [Bn * 8];  // waiter tickets (8 conv blocks per batch per epoch)

// ---- PTX helpers ----
__device__ __forceinline__ unsigned s2u(const void* p) {
    unsigned a;
    asm("{ .reg .u64 t; cvta.to.shared.u64 t, %1; cvt.u32.u64 %0, t; }"
        : "=r"(a) : "l"(p));
    return a;
}
#define MBINIT(addr, cnt) \
    asm volatile("mbarrier.init.shared.b64 [%0], %1;" :: "r"(addr), "r"(cnt) : "memory")
#define MBEXPECT(addr, tx) \
    asm volatile("mbarrier.arrive.expect_tx.shared.b64 _, [%0], %1;" :: "r"(addr), "r"(tx) : "memory")
#define BULKCP(dst, src, sz, mbar) \
    asm volatile("cp.async.bulk.shared::cta.global.mbarrier::complete_tx::bytes [%0], [%1], %2, [%3];" \
                 :: "r"(dst), "l"(src), "r"(sz), "r"(mbar) : "memory")
#define MBWAIT(mbar_addr, parity) do { \
    unsigned _m = (mbar_addr), _p = (parity), _d; \
    asm volatile("{ .reg .pred p; mbarrier.try_wait.parity.acquire.cta.shared::cta.b64 p, [%1], %2; selp.b32 %0, 1, 0, p; }" \
        : "=r"(_d) : "r"(_m), "r"(_p) : "memory"); \
    if (!_d) { \
        asm volatile("{ .reg .pred P1; WL_%=: mbarrier.try_wait.parity.acquire.cta.shared::cta.b64 P1, [%0], %1, 0x989680; @P1 bra.uni WD_%=; bra.uni WL_%=; WD_%=: }" \
            :: "r"(_m), "r"(_p) : "memory"); \
    } \
} while (0)

// ============================================================
// K1: block 0 = spectral norms; blocks 1..4096 = stats via
// cp.async.bulk double-buffered pipeline (R16-measured best).
// grid = 4097, block = 512.
// ============================================================
__global__ void __launch_bounds__(512)
k_stats(const float* __restrict__ x,
        const float* __restrict__ w1, const float* __restrict__ u1,
        const float* __restrict__ w2, const float* __restrict__ u2,
        const float* __restrict__ w3) {
    int t = threadIdx.x;
    __shared__ alignas(128) float stage[2 * 4096];     // 2 x 16 KB
    __shared__ alignas(8) unsigned long long mbar[2];

    if (blockIdx.x == 0) {
        // ---------------- spectral norms, 512 threads ----------------
        __shared__ float buf[Cn];
        __shared__ float red[Cn];
        int o8 = t >> 3, k8 = t & 7;

        // ----- sv1 : Wm1 [64, 512] -----
        float v = 0.f;
#pragma unroll 8
        for (int i = 0; i < CR; i++) v += u1[i] * w1[i * Cn + t];
        red[t] = v * v;
        __syncthreads();
        for (int o = 256; o; o >>= 1) { if (t < o) red[t] += red[t + o]; __syncthreads(); }
        float nv = sqrtf(red[0]);
        __syncthreads();
        buf[t] = v / fmaxf(nv, EPS);
        __syncthreads();
        {
            float tv = 0.f;
#pragma unroll 8
            for (int j = k8 * 64; j < k8 * 64 + 64; j++) tv += w1[o8 * Cn + j] * buf[j];
#pragma unroll
            for (int o = 4; o; o >>= 1) tv += __shfl_down_sync(0xffffffffu, tv, o, 8);
            __syncthreads();
            if (k8 == 0) red[o8] = tv * tv;
            __syncthreads();
            if (t < 32) {
                float r = red[t] + red[t + 32];
#pragma unroll
                for (int o = 16; o; o >>= 1) r += __shfl_down_sync(0xffffffffu, r, o);
                if (t == 0) { float nt = sqrtf(r); g_sv[0] = nt * nt / fmaxf(nt, EPS); }
            }
            __syncthreads();
        }

        // ----- sv2 : Wm2 [512, 64] -----
        {
            float v2 = 0.f;
#pragma unroll 8
            for (int i = k8 * 64; i < k8 * 64 + 64; i++) v2 += u2[i] * w2[i * CR + o8];
#pragma unroll
            for (int o = 4; o; o >>= 1) v2 += __shfl_down_sync(0xffffffffu, v2, o, 8);
            __syncthreads();
            if (k8 == 0) red[o8] = v2 * v2;
            __syncthreads();
            if (t < 32) {
                float r = red[t] + red[t + 32];
#pragma unroll
                for (int o = 16; o; o >>= 1) r += __shfl_down_sync(0xffffffffu, r, o);
                if (t == 0) red[0] = sqrtf(r);
            }
            __syncthreads();
            float n2 = red[0];
            __syncthreads();
            if (k8 == 0) buf[o8] = v2 / fmaxf(n2, EPS);
            __syncthreads();
            float t2 = 0.f;
#pragma unroll 8
            for (int j = 0; j < CR; j++) t2 += w2[t * CR + j] * buf[j];
            red[t] = t2 * t2;
            __syncthreads();
            for (int o = 256; o; o >>= 1) { if (t < o) red[t] += red[t + o]; __syncthreads(); }
            if (t == 0) { float nt = sqrtf(red[0]); g_sv[1] = nt * nt / fmaxf(nt, EPS); }
        }

        // ----- sv3 = ||w3||_F -----
        if (t == 0) {
            float nn = 0.f;
            for (int k = 0; k < 18; k++) nn += w3[k] * w3[k];
            g_sv[2] = sqrtf(nn);
        }
        return;
    }

    // ---------------- stats: bulk-copy pipeline, 4 rows/block ----------------
    int idx = blockIdx.x - 1;                 // 0..4095
    int bc0 = idx * 4;
    const char* src = reinterpret_cast<const char*>(x) + (size_t)bc0 * HW * 4;
    unsigned sb = s2u(stage);
    unsigned mb0 = s2u(&mbar[0]);
    unsigned mb1 = s2u(&mbar[1]);

    if (t == 0) { MBINIT(mb0, 1); MBINIT(mb1, 1); }
    __syncthreads();
    if (t == 0) {
        MBEXPECT(mb0, 16384u); BULKCP(sb,          src,         16384u, mb0);
        MBEXPECT(mb1, 16384u); BULKCP(sb + 16384u, src + 16384, 16384u, mb1);
    }

    float sa[4], ma[4];
#pragma unroll
    for (int s = 0; s < 4; s++) { sa[s] = 0.f; ma[s] = -FLT_MAX; }

#pragma unroll
    for (int s = 0; s < 4; s++) {
        unsigned m = (s & 1) ? mb1 : mb0;
        MBWAIT(m, (unsigned)(s >> 1));
        const float4* buf4 = reinterpret_cast<const float4*>(stage + (s & 1) * 4096);
        float4 v0 = buf4[t];
        float4 v1 = buf4[512 + t];
        sa[s] += ((v0.x + v0.y) + (v0.z + v0.w)) + ((v1.x + v1.y) + (v1.z + v1.w));
        float mm = fmaxf(fmaxf(fmaxf(v0.x, v0.y), fmaxf(v0.z, v0.w)),
                         fmaxf(fmaxf(v1.x, v1.y), fmaxf(v1.z, v1.w)));
        ma[s] = fmaxf(ma[s], mm);
        __syncthreads();
        if (s < 2 && t == 0) {
            MBEXPECT(m, 16384u);
            BULKCP(sb + (unsigned)(s & 1) * 16384u, src + (size_t)(s + 2) * 16384, 16384u, m);
        }
    }

    // ---- tail reduce ----
#pragma unroll
    for (int o = 16; o; o >>= 1) {
        sa[0] += __shfl_down_sync(0xffffffffu, sa[0], o);
        sa[1] += __shfl_down_sync(0xffffffffu, sa[1], o);
        sa[2] += __shfl_down_sync(0xffffffffu, sa[2], o);
        sa[3] += __shfl_down_sync(0xffffffffu, sa[3], o);
        ma[0] = fmaxf(ma[0], __shfl_down_sync(0xffffffffu, ma[0], o));
        ma[1] = fmaxf(ma[1], __shfl_down_sync(0xffffffffu, ma[1], o));
        ma[2] = fmaxf(ma[2], __shfl_down_sync(0xffffffffu, ma[2], o));
        ma[3] = fmaxf(ma[3], __shfl_down_sync(0xffffffffu, ma[3], o));
    }
    __shared__ float wsum[16][4];
    __shared__ float wmax[16][4];
    int warp = t >> 5, lane = t & 31;
    if (lane == 0) {
#pragma unroll
        for (int r = 0; r < 4; r++) { wsum[warp][r] = sa[r]; wmax[warp][r] = ma[r]; }
    }
    __syncthreads();
    if (warp < 4 && lane < 16) {
        float a = wsum[lane][warp];
        float b = wmax[lane][warp];
#pragma unroll
        for (int o = 8; o; o >>= 1) {
            a += __shfl_down_sync(0x0000ffffu, a, o, 16);
            b = fmaxf(b, __shfl_down_sync(0x0000ffffu, b, o, 16));
        }
        if (lane == 0) {
            g_avg[bc0 + warp] = a * (1.f / HW);
            g_mx [bc0 + warp] = b;
        }
    }
}

// ============================================================
// K2: channel-attention MLP + sigmoid -> s[B,C]. (sv precomputed)
// grid = 32, block = 512. Hidden layer: 8 threads per output.
// ============================================================
__global__ void k_mlp(const float* __restrict__ w1, const float* __restrict__ b1,
                      const float* __restrict__ w2, const float* __restrict__ b2) {
    int b = blockIdx.x, t = threadIdx.x;
    int o8 = t >> 3, k8 = t & 7;
    __shared__ float sa[Cn], sx[Cn], ha[CR], hm[CR];
    sa[t] = g_avg[b * Cn + t];
    sx[t] = g_mx [b * Cn + t];
    __syncthreads();
    float inv1 = 1.f / g_sv[0];
    float inv2 = 1.f / g_sv[1];
    {
        float xa = 0.f, xm = 0.f;
#pragma unroll 8
        for (int c = k8 * 64; c < k8 * 64 + 64; c++) {
            float w = w1[o8 * Cn + c];
            xa += w * sa[c];
            xm += w * sx[c];
        }
#pragma unroll
        for (int o = 4; o; o >>= 1) {
            xa += __shfl_down_sync(0xffffffffu, xa, o, 8);
            xm += __shfl_down_sync(0xffffffffu, xm, o, 8);
        }
        if (k8 == 0) {
            float bb = b1[o8];
            ha[o8] = fmaxf(xa * inv1 + bb, 0.f);
            hm[o8] = fmaxf(xm * inv1 + bb, 0.f);
        }
    }
    __syncthreads();
    float a = 0.f, m = 0.f;
#pragma unroll 8
    for (int k = 0; k < CR; k++) {
        float w = w2[t * CR + k];
        a += w * ha[k];
        m += w * hm[k];
    }
    float bb = b2[t];
    a = a * inv2 + bb;
    m = m * inv2 + bb;
    g_s[b * Cn + t] = 1.f / (1.f + expf(-(a + m)));
}

// ============================================================
// K3: grid = (40, 32), block = 512.
//  x in [0,32)  : pool — per-pixel mean/max of x*s -> ca, cm
//                 (measured shape: 77% DRAM); bumps c_pool[b]
//  x in [32,40) : conv slot — ticket-waits on c_pool[b], 512 px
//                 each, 3x3 conv + sigmoid -> g_sig
// ============================================================
__global__ void __launch_bounds__(512)
k_pool(const float* __restrict__ x, const float* __restrict__ w3,
       const float* __restrict__ b3) {
    int b = blockIdx.y;
    int tid = threadIdx.x;

    if (blockIdx.x < 32) {
        int p0 = blockIdx.x * 128;           // 128 pixels per block
        int g  = tid & 31;                   // float4 pixel-group 0..31
        int ch = tid >> 5;                   // channel-chunk 0..15
        __shared__ float ss[Cn];
        __shared__ float4 rs[16][32];
        __shared__ float4 rm[16][32];
        ss[tid] = g_s[b * Cn + tid];
        __syncthreads();

        const float* xb = x + (size_t)b * Cn * HW + p0 + g * 4;
        float4 sum = make_float4(0.f, 0.f, 0.f, 0.f);
        float4 mx  = make_float4(-FLT_MAX, -FLT_MAX, -FLT_MAX, -FLT_MAX);
#pragma unroll 8
        for (int cc = 0; cc < 32; cc++) {
            int c = ch * 32 + cc;
            float4 v = *reinterpret_cast<const float4*>(xb + (size_t)c * HW);
            float s = ss[c];
            v.x *= s; v.y *= s; v.z *= s; v.w *= s;
            sum.x += v.x; sum.y += v.y; sum.z += v.z; sum.w += v.w;
            mx.x = fmaxf(mx.x, v.x); mx.y = fmaxf(mx.y, v.y);
            mx.z = fmaxf(mx.z, v.z); mx.w = fmaxf(mx.w, v.w);
        }
        rs[ch][g] = sum; rm[ch][g] = mx;
        __syncthreads();
#pragma unroll
        for (int o = 8; o; o >>= 1) {
            if (ch < o) {
                float4 a = rs[ch][g], c2 = rs[ch + o][g];
                a.x += c2.x; a.y += c2.y; a.z += c2.z; a.w += c2.w;
                rs[ch][g] = a;
                float4 m1 = rm[ch][g], m2 = rm[ch + o][g];
                m1.x = fmaxf(m1.x, m2.x); m1.y = fmaxf(m1.y, m2.y);
                m1.z = fmaxf(m1.z, m2.z); m1.w = fmaxf(m1.w, m2.w);
                rm[ch][g] = m1;
            }
            __syncthreads();
        }
        if (ch == 0) {
            float4 a = rs[0][g];
            a.x *= (1.f / Cn); a.y *= (1.f / Cn); a.z *= (1.f / Cn); a.w *= (1.f / Cn);
            *reinterpret_cast<float4*>(g_ca + b * HW + p0 + g * 4) = a;
            *reinterpret_cast<float4*>(g_cm + b * HW + p0 + g * 4) = rm[0][g];
        }
        __syncthreads();
        if (tid == 0) {
            __threadfence();
            atomicAdd(&c_pool[b], 1u);
        }
        return;
    }

    // ---------------- conv slot ----------------
    {
        int slot = blockIdx.x - 32;          // 0..7
        __shared__ float wc[20];
        if (tid < 18) wc[tid] = w3[tid];
        if (tid == 18) wc[18] = b3[0];
        if (tid == 19) wc[19] = 1.f / g_sv[2];
        if (tid == 0) {
            unsigned e = atomicAdd(&t_conv[b * 8 + slot], 1u);
            unsigned target = (e + 1u) * 32u;
            volatile unsigned* p = &c_pool[b];
            while ((int)(*p - target) < 0) __nanosleep(64);
            __threadfence();
        }
        __syncthreads();

        int p = slot * 512 + tid;
        int h = p >> 6, w = p & 63;
        const float* ca = g_ca + b * HW;
        const float* cm = g_cm + b * HW;
        float y = 0.f;
#pragma unroll
        for (int dy = -1; dy <= 1; dy++) {
            int hh = h + dy;
            if (hh < 0 || hh >= Hd) continue;
#pragma unroll
            for (int dx = -1; dx <= 1; dx++) {
                int ww = w + dx;
                if (ww < 0 || ww >= Wd) continue;
                int q = hh * Wd + ww;
                int ki = (dy + 1) * 3 + (dx + 1);
                y += wc[ki] * ca[q] + wc[9 + ki] * cm[q];
            }
        }
        y = y * wc[19] + wc[18];
        g_sig[b * HW + p] = 1.f / (1.f + expf(-y));
    }
}

// ============================================================
// K4: pointwise out = x * s[b,c] * sig[b,p], 2 channels/block.
// (measured best: 76.2us @ 80.4% DRAM). grid = 8192, block = 256.
// ============================================================
__global__ void k_out(const float* __restrict__ x, float* __restrict__ out) {
    int blk = blockIdx.x;                // 0..8191
    int b = blk >> 8;                    // /256
    int c0 = (blk & 255) * 2;
    float s0 = g_s[b * Cn + c0];
    float s1 = g_s[b * Cn + c0 + 1];
    const float4* x0 = reinterpret_cast<const float4*>(x + ((size_t)b * Cn + c0) * HW);
    const float4* x1 = x0 + HW / 4;
    float4* o0 = reinterpret_cast<float4*>(out + ((size_t)b * Cn + c0) * HW);
    float4* o1 = o0 + HW / 4;
    const float4* sg = reinterpret_cast<const float4*>(g_sig + b * HW);
    int tid = threadIdx.x;
#pragma unroll
    for (int k = 0; k < 4; k++) {
        int i = k * 256 + tid;
        float4 gv = sg[i];
        float4 v0 = __ldcs(x0 + i);
        float4 v1 = __ldcs(x1 + i);
        v0.x *= s0 * gv.x; v0.y *= s0 * gv.y; v0.z *= s0 * gv.z; v0.w *= s0 * gv.w;
        v1.x *= s1 * gv.x; v1.y *= s1 * gv.y; v1.z *= s1 * gv.z; v1.w *= s1 * gv.w;
        __stcs(o0 + i, v0);
        __stcs(o1 + i, v1);
    }
}

// ============================================================
extern "C" void kernel_launch(void* const* d_in, const int* in_sizes, int n_in,
                              void* d_out, int out_size) {
    const float* x  = (const float*)d_in[0];
    const float* w1 = (const float*)d_in[1];
    const float* b1 = (const float*)d_in[2];
    const float* u1 = (const float*)d_in[3];
    const float* w2 = (const float*)d_in[4];
    const float* b2 = (const float*)d_in[5];
    const float* u2 = (const float*)d_in[6];
    const float* w3 = (const float*)d_in[7];
    const float* b3 = (const float*)d_in[8];
    // d_in[9] = u3: unused (sv3 reduces to ||w3||_F)
    float* out = (float*)d_out;

    k_stats<<<1 + Bn * Cn / 4, 512>>>(x, w1, u1, w2, u2, w3);
    k_mlp<<<Bn, Cn>>>(w1, b1, w2, b2);
    k_pool<<<dim3(40, Bn), 512>>>(x, w3, b3);
    k_out<<<Bn * Cn / 2, 256>>>(x, out);
}